// round 3
// baseline (speedup 1.0000x reference)
#include <cuda_runtime.h>
#include <math.h>

#define NB 64
#define NF 500
#define NT 1024
#define NO 10
#define NFS 4            // F-splits
#define FSL (NF / NFS)   // 125 features per split

// Partial sums: g_u[fs][b][o][t]
__device__ float g_u[NFS * NB * NO * NT];

__device__ __forceinline__ float sigmoid_acc(float x) {
    return 1.0f / (1.0f + expf(-x));
}

// Kernel 1: partial projection over one F-slice.
// Grid: (NT/256, NB, NFS); 64 threads/block; each thread owns 4 consecutive t.
__global__ __launch_bounds__(64) void proj_kernel(const float* __restrict__ in,
                                                  const float* __restrict__ W) {
    __shared__ float Wp[FSL * 12];  // 12 floats/feature pad for float4 LDS
    const int tid = threadIdx.x;
    const int fs  = blockIdx.z;

    for (int i = tid; i < FSL * 12; i += 64) Wp[i] = 0.0f;
    __syncthreads();
    for (int i = tid; i < FSL * NO; i += 64) {
        int f = i / NO, o = i - f * NO;
        Wp[f * 12 + o] = W[o * NF + fs * FSL + f];
    }
    __syncthreads();

    const int b  = blockIdx.y;
    const int t0 = blockIdx.x * 256 + tid * 4;

    float acc0[NO], acc1[NO], acc2[NO], acc3[NO];
#pragma unroll
    for (int o = 0; o < NO; o++) {
        acc0[o] = 0.0f; acc1[o] = 0.0f; acc2[o] = 0.0f; acc3[o] = 0.0f;
    }

    const float* base = in + ((size_t)(b * NF + fs * FSL)) * NT + t0;

#pragma unroll 5
    for (int f = 0; f < FSL; f++) {
        float4 xv = *(const float4*)(base + (size_t)f * NT);
        float s0 = sigmoid_acc(xv.x);
        float s1 = sigmoid_acc(xv.y);
        float s2 = sigmoid_acc(xv.z);
        float s3 = sigmoid_acc(xv.w);
        const float4* wv = (const float4*)&Wp[f * 12];
        float4 w0 = wv[0];
        float4 w1 = wv[1];
        float4 w2 = wv[2];
        acc0[0] = fmaf(s0, w0.x, acc0[0]); acc1[0] = fmaf(s1, w0.x, acc1[0]);
        acc2[0] = fmaf(s2, w0.x, acc2[0]); acc3[0] = fmaf(s3, w0.x, acc3[0]);
        acc0[1] = fmaf(s0, w0.y, acc0[1]); acc1[1] = fmaf(s1, w0.y, acc1[1]);
        acc2[1] = fmaf(s2, w0.y, acc2[1]); acc3[1] = fmaf(s3, w0.y, acc3[1]);
        acc0[2] = fmaf(s0, w0.z, acc0[2]); acc1[2] = fmaf(s1, w0.z, acc1[2]);
        acc2[2] = fmaf(s2, w0.z, acc2[2]); acc3[2] = fmaf(s3, w0.z, acc3[2]);
        acc0[3] = fmaf(s0, w0.w, acc0[3]); acc1[3] = fmaf(s1, w0.w, acc1[3]);
        acc2[3] = fmaf(s2, w0.w, acc2[3]); acc3[3] = fmaf(s3, w0.w, acc3[3]);
        acc0[4] = fmaf(s0, w1.x, acc0[4]); acc1[4] = fmaf(s1, w1.x, acc1[4]);
        acc2[4] = fmaf(s2, w1.x, acc2[4]); acc3[4] = fmaf(s3, w1.x, acc3[4]);
        acc0[5] = fmaf(s0, w1.y, acc0[5]); acc1[5] = fmaf(s1, w1.y, acc1[5]);
        acc2[5] = fmaf(s2, w1.y, acc2[5]); acc3[5] = fmaf(s3, w1.y, acc3[5]);
        acc0[6] = fmaf(s0, w1.z, acc0[6]); acc1[6] = fmaf(s1, w1.z, acc1[6]);
        acc2[6] = fmaf(s2, w1.z, acc2[6]); acc3[6] = fmaf(s3, w1.z, acc3[6]);
        acc0[7] = fmaf(s0, w1.w, acc0[7]); acc1[7] = fmaf(s1, w1.w, acc1[7]);
        acc2[7] = fmaf(s2, w1.w, acc2[7]); acc3[7] = fmaf(s3, w1.w, acc3[7]);
        acc0[8] = fmaf(s0, w2.x, acc0[8]); acc1[8] = fmaf(s1, w2.x, acc1[8]);
        acc2[8] = fmaf(s2, w2.x, acc2[8]); acc3[8] = fmaf(s3, w2.x, acc3[8]);
        acc0[9] = fmaf(s0, w2.y, acc0[9]); acc1[9] = fmaf(s1, w2.y, acc1[9]);
        acc2[9] = fmaf(s2, w2.y, acc2[9]); acc3[9] = fmaf(s3, w2.y, acc3[9]);
    }

#pragma unroll
    for (int o = 0; o < NO; o++) {
        float* p = g_u + ((size_t)((fs * NB + b) * NO + o)) * NT + t0;
        *(float4*)p = make_float4(acc0[o], acc1[o], acc2[o], acc3[o]);
    }
}

// Kernel 2: sum the 4 partials, then per-(b,o) dual-exp IIR + LIF scan over T.
__global__ __launch_bounds__(128) void scan_kernel(const float* __restrict__ a1p,
                                                   const float* __restrict__ a2p,
                                                   const float* __restrict__ bias,
                                                   float* __restrict__ out) {
    const int idx = blockIdx.x * blockDim.x + threadIdx.x;
    if (idx >= NB * NO) return;
    const int o = idx % NO;

    const float a1 = a1p[0];
    const float a2 = a2p[0];
    const float dm = 0.7788007830714049f;  // exp(-1/4) as f32
    const float bo = bias[o];

    const float* u0 = g_u + (size_t)idx * NT;
    const float* u1 = u0 + (size_t)NB * NO * NT;
    const float* u2 = u1 + (size_t)NB * NO * NT;
    const float* u3 = u2 + (size_t)NB * NO * NT;
    float* op = out + (size_t)idx * NT;

    float y1 = 0.0f, y2 = 0.0f;   // IIR state
    float v = 0.0f;               // LIF membrane

    for (int t = 0; t < NT; t += 4) {
        float4 p0 = *(const float4*)(u0 + t);
        float4 p1 = *(const float4*)(u1 + t);
        float4 p2 = *(const float4*)(u2 + t);
        float4 p3 = *(const float4*)(u3 + t);
        float4 u4;
        u4.x = (p0.x + p1.x) + (p2.x + p3.x);
        u4.y = (p0.y + p1.y) + (p2.y + p3.y);
        u4.z = (p0.z + p1.z) + (p2.z + p3.z);
        u4.w = (p0.w + p1.w) + (p2.w + p3.w);
        float4 s4;

        {
            float y = fmaf(a1, y1, fmaf(a2, y2, u4.x));
            y2 = y1; y1 = y;
            float it = y + bo;
            float vn = fmaf(dm, v, it);
            v = (v > 1.0f) ? it : vn;      // reset-on-spike (prev v's spike)
            s4.x = (v > 1.0f) ? 1.0f : 0.0f;
        }
        {
            float y = fmaf(a1, y1, fmaf(a2, y2, u4.y));
            y2 = y1; y1 = y;
            float it = y + bo;
            float vn = fmaf(dm, v, it);
            v = (v > 1.0f) ? it : vn;
            s4.y = (v > 1.0f) ? 1.0f : 0.0f;
        }
        {
            float y = fmaf(a1, y1, fmaf(a2, y2, u4.z));
            y2 = y1; y1 = y;
            float it = y + bo;
            float vn = fmaf(dm, v, it);
            v = (v > 1.0f) ? it : vn;
            s4.z = (v > 1.0f) ? 1.0f : 0.0f;
        }
        {
            float y = fmaf(a1, y1, fmaf(a2, y2, u4.w));
            y2 = y1; y1 = y;
            float it = y + bo;
            float vn = fmaf(dm, v, it);
            v = (v > 1.0f) ? it : vn;
            s4.w = (v > 1.0f) ? 1.0f : 0.0f;
        }

        *(float4*)(op + t) = s4;
    }
}

extern "C" void kernel_launch(void* const* d_in, const int* in_sizes, int n_in,
                              void* d_out, int out_size) {
    const float* in = (const float*)d_in[0];   // [64, 500, 1024]
    const float* a1 = (const float*)d_in[1];   // [500]
    const float* a2 = (const float*)d_in[2];   // [500]
    const float* W  = (const float*)d_in[3];   // [10, 500]
    const float* b  = (const float*)d_in[4];   // [10]
    float* out = (float*)d_out;                // [64, 10, 1024]

    dim3 grid1(NT / 256, NB, NFS);
    proj_kernel<<<grid1, 64>>>(in, W);
    scan_kernel<<<(NB * NO + 127) / 128, 128>>>(a1, a2, b, out);
}

// round 6
// speedup vs baseline: 3.3172x; 3.3172x over previous
#include <cuda_runtime.h>
#include <math.h>

#define NB 64
#define NF 500
#define NT 1024
#define NO 10
#define NFS 4            // F-splits
#define FSL (NF / NFS)   // 125 features per split

// Partial sums: g_u[fs][b][o][t]
__device__ float g_u[NFS * NB * NO * NT];

__device__ __forceinline__ float sigmoid_fast(float x) {
    // sigma(x) = 0.5*tanh(0.5x) + 0.5   (MUFU.TANH, sm_75+)
    float th;
    asm("tanh.approx.f32 %0, %1;" : "=f"(th) : "f"(0.5f * x));
    return fmaf(0.5f, th, 0.5f);
}

#if defined(__CUDA_ARCH__) && (__CUDA_ARCH__ >= 1000)
#define USE_F32X2 1
#else
#define USE_F32X2 0
#endif

__device__ __forceinline__ unsigned long long pack2(float lo, float hi) {
    unsigned long long v;
    asm("mov.b64 %0, {%1, %2};" : "=l"(v) : "f"(lo), "f"(hi));
    return v;
}

__device__ __forceinline__ void unpack2(unsigned long long v, float& lo, float& hi) {
    asm("mov.b64 {%0, %1}, %2;" : "=f"(lo), "=f"(hi) : "l"(v));
}

__device__ __forceinline__ void fma2(unsigned long long& d, unsigned long long a,
                                     unsigned long long b) {
#if USE_F32X2
    // packed f32x2 FMA: d = a*b + d  (SASS FFMA2)
    asm("fma.rn.f32x2 %0, %1, %2, %0;" : "+l"(d) : "l"(a), "l"(b));
#else
    float dl, dh, al, ah, bl, bh;
    unpack2(d, dl, dh); unpack2(a, al, ah); unpack2(b, bl, bh);
    dl = fmaf(al, bl, dl); dh = fmaf(ah, bh, dh);
    d = pack2(dl, dh);
#endif
}

// Kernel 1: partial projection over one F-slice.
// Grid: (NT/256, NB, NFS); 64 threads/block; each thread owns 4 consecutive t.
__global__ __launch_bounds__(64) void proj_kernel(const float* __restrict__ in,
                                                  const float* __restrict__ W) {
    // weights duplicated: Wp2[f*10 + o] = (w, w) for packed FMA
    __shared__ __align__(16) float2 Wp2[FSL * NO];
    const int tid = threadIdx.x;
    const int fs  = blockIdx.z;

    for (int i = tid; i < FSL * NO; i += 64) {
        int f = i / NO, o = i - f * NO;
        float w = W[o * NF + fs * FSL + f];
        Wp2[f * NO + o] = make_float2(w, w);
    }
    __syncthreads();

    const int b  = blockIdx.y;
    const int t0 = blockIdx.x * 256 + tid * 4;

    unsigned long long acc01[NO], acc23[NO];
#pragma unroll
    for (int o = 0; o < NO; o++) { acc01[o] = 0ULL; acc23[o] = 0ULL; }

    const float* base = in + ((size_t)(b * NF + fs * FSL)) * NT + t0;

#pragma unroll 5
    for (int f = 0; f < FSL; f++) {
        float4 xv = *(const float4*)(base + (size_t)f * NT);
        float s0 = sigmoid_fast(xv.x);
        float s1 = sigmoid_fast(xv.y);
        float s2 = sigmoid_fast(xv.z);
        float s3 = sigmoid_fast(xv.w);
        unsigned long long s01 = pack2(s0, s1);
        unsigned long long s23 = pack2(s2, s3);

        const ulonglong2* wv = (const ulonglong2*)&Wp2[f * NO];
        ulonglong2 wa = wv[0];  // o0, o1
        ulonglong2 wb = wv[1];  // o2, o3
        ulonglong2 wc = wv[2];  // o4, o5
        ulonglong2 wd = wv[3];  // o6, o7
        ulonglong2 we = wv[4];  // o8, o9

        fma2(acc01[0], s01, wa.x); fma2(acc23[0], s23, wa.x);
        fma2(acc01[1], s01, wa.y); fma2(acc23[1], s23, wa.y);
        fma2(acc01[2], s01, wb.x); fma2(acc23[2], s23, wb.x);
        fma2(acc01[3], s01, wb.y); fma2(acc23[3], s23, wb.y);
        fma2(acc01[4], s01, wc.x); fma2(acc23[4], s23, wc.x);
        fma2(acc01[5], s01, wc.y); fma2(acc23[5], s23, wc.y);
        fma2(acc01[6], s01, wd.x); fma2(acc23[6], s23, wd.x);
        fma2(acc01[7], s01, wd.y); fma2(acc23[7], s23, wd.y);
        fma2(acc01[8], s01, we.x); fma2(acc23[8], s23, we.x);
        fma2(acc01[9], s01, we.y); fma2(acc23[9], s23, we.y);
    }

#pragma unroll
    for (int o = 0; o < NO; o++) {
        float4 r;
        unpack2(acc01[o], r.x, r.y);
        unpack2(acc23[o], r.z, r.w);
        float* p = g_u + ((size_t)((fs * NB + b) * NO + o)) * NT + t0;
        *(float4*)p = r;
    }
}

// Kernel 2: one block per (b,o) sequence. Coop-load partials into shared,
// single-thread IIR+LIF scan from shared, coop-store spikes.
__global__ __launch_bounds__(256) void scan_kernel(const float* __restrict__ a1p,
                                                   const float* __restrict__ a2p,
                                                   const float* __restrict__ bias,
                                                   float* __restrict__ out) {
    __shared__ __align__(16) float ps[NT];
    __shared__ __align__(16) float sp[NT];

    const int blk = blockIdx.x;           // 0..NB*NO-1  (= b*NO + o)
    const int tid = threadIdx.x;
    const int o = blk % NO;

    const size_t stride = (size_t)NB * NO * NT;
    const float* u0 = g_u + (size_t)blk * NT;
    const float* u1 = u0 + stride;
    const float* u2 = u1 + stride;
    const float* u3 = u2 + stride;

    // cooperative load + sum of the 4 partials into shared (one float4 per thread)
    {
        int t = tid * 4;
        float4 p0 = *(const float4*)(u0 + t);
        float4 p1 = *(const float4*)(u1 + t);
        float4 p2 = *(const float4*)(u2 + t);
        float4 p3 = *(const float4*)(u3 + t);
        float4 s;
        s.x = (p0.x + p1.x) + (p2.x + p3.x);
        s.y = (p0.y + p1.y) + (p2.y + p3.y);
        s.z = (p0.z + p1.z) + (p2.z + p3.z);
        s.w = (p0.w + p1.w) + (p2.w + p3.w);
        *(float4*)(ps + t) = s;
    }
    __syncthreads();

    if (tid == 0) {
        const float a1 = a1p[0];
        const float a2 = a2p[0];
        const float dm = 0.7788007830714049f;  // exp(-1/4) as f32
        const float bo = bias[o];

        float y1 = 0.0f, y2 = 0.0f;   // IIR state
        float v = 0.0f;               // LIF membrane

#pragma unroll 4
        for (int t = 0; t < NT; t += 4) {
            float4 u4 = *(const float4*)(ps + t);
            float4 s4;
            {
                float y = fmaf(a1, y1, fmaf(a2, y2, u4.x));
                y2 = y1; y1 = y;
                float it = y + bo;
                float vn = fmaf(dm, v, it);
                v = (v > 1.0f) ? it : vn;      // reset-on-spike (prev v's spike)
                s4.x = (v > 1.0f) ? 1.0f : 0.0f;
            }
            {
                float y = fmaf(a1, y1, fmaf(a2, y2, u4.y));
                y2 = y1; y1 = y;
                float it = y + bo;
                float vn = fmaf(dm, v, it);
                v = (v > 1.0f) ? it : vn;
                s4.y = (v > 1.0f) ? 1.0f : 0.0f;
            }
            {
                float y = fmaf(a1, y1, fmaf(a2, y2, u4.z));
                y2 = y1; y1 = y;
                float it = y + bo;
                float vn = fmaf(dm, v, it);
                v = (v > 1.0f) ? it : vn;
                s4.z = (v > 1.0f) ? 1.0f : 0.0f;
            }
            {
                float y = fmaf(a1, y1, fmaf(a2, y2, u4.w));
                y2 = y1; y1 = y;
                float it = y + bo;
                float vn = fmaf(dm, v, it);
                v = (v > 1.0f) ? it : vn;
                s4.w = (v > 1.0f) ? 1.0f : 0.0f;
            }
            *(float4*)(sp + t) = s4;
        }
    }
    __syncthreads();

    float* op = out + (size_t)blk * NT;
    {
        int t = tid * 4;
        *(float4*)(op + t) = *(const float4*)(sp + t);
    }
}

extern "C" void kernel_launch(void* const* d_in, const int* in_sizes, int n_in,
                              void* d_out, int out_size) {
    const float* in = (const float*)d_in[0];   // [64, 500, 1024]
    const float* a1 = (const float*)d_in[1];   // [500]
    const float* a2 = (const float*)d_in[2];   // [500]
    const float* W  = (const float*)d_in[3];   // [10, 500]
    const float* b  = (const float*)d_in[4];   // [10]
    float* out = (float*)d_out;                // [64, 10, 1024]

    dim3 grid1(NT / 256, NB, NFS);
    proj_kernel<<<grid1, 64>>>(in, W);
    scan_kernel<<<NB * NO, 256>>>(a1, a2, b, out);
}

// round 9
// speedup vs baseline: 3.7858x; 1.1413x over previous
#include <cuda_runtime.h>
#include <math.h>

#define NB 64
#define NF 500
#define NT 1024
#define NO 10
#define NFS 4            // F-splits
#define FSL (NF / NFS)   // 125 features per split

// Partial sums: g_u[fs][b][o][t]
__device__ float g_u[NFS * NB * NO * NT];

__device__ __forceinline__ float tanh_fast(float x) {
    float th;
    asm("tanh.approx.f32 %0, %1;" : "=f"(th) : "f"(x));
    return th;
}

#if defined(__CUDA_ARCH__) && (__CUDA_ARCH__ >= 1000)
#define USE_F32X2 1
#else
#define USE_F32X2 0
#endif

__device__ __forceinline__ unsigned long long pack2(float lo, float hi) {
    unsigned long long v;
    asm("mov.b64 %0, {%1, %2};" : "=l"(v) : "f"(lo), "f"(hi));
    return v;
}

__device__ __forceinline__ void unpack2(unsigned long long v, float& lo, float& hi) {
    asm("mov.b64 {%0, %1}, %2;" : "=f"(lo), "=f"(hi) : "l"(v));
}

__device__ __forceinline__ void fma2(unsigned long long& d, unsigned long long a,
                                     unsigned long long b) {
#if USE_F32X2
    asm("fma.rn.f32x2 %0, %1, %2, %0;" : "+l"(d) : "l"(a), "l"(b));
#else
    float dl, dh, al, ah, bl, bh;
    unpack2(d, dl, dh); unpack2(a, al, ah); unpack2(b, bl, bh);
    dl = fmaf(al, bl, dl); dh = fmaf(ah, bh, dh);
    d = pack2(dl, dh);
#endif
}

// Kernel 1: partial projection over one F-slice.
// Grid: (NT/128, NB, NFS); 64 threads/block; each thread owns 2 consecutive t.
// psc_o = sum_f (0.5*w_of)*tanh(0.5*x_f) + C_o,  C_o = sum_f 0.5*w_of
__global__ __launch_bounds__(64) void proj_kernel(const float* __restrict__ in,
                                                  const float* __restrict__ W) {
    // halved weights duplicated: Wp2[f*10 + o] = (0.5w, 0.5w)
    __shared__ __align__(16) float2 Wp2[FSL * NO];
    __shared__ float Cs[NO];
    const int tid = threadIdx.x;
    const int fs  = blockIdx.z;

    for (int i = tid; i < FSL * NO; i += 64) {
        int f = i / NO, o = i - f * NO;
        float w = 0.5f * W[o * NF + fs * FSL + f];
        Wp2[f * NO + o] = make_float2(w, w);
    }
    __syncthreads();
    if (tid < NO) {
        float c = 0.0f;
        for (int f = 0; f < FSL; f++) c += Wp2[f * NO + tid].x;
        Cs[tid] = c;
    }
    __syncthreads();

    const int b  = blockIdx.y;
    const int t0 = blockIdx.x * 128 + tid * 2;

    unsigned long long acc[NO];
#pragma unroll
    for (int o = 0; o < NO; o++) acc[o] = 0ULL;

    const float* base = in + ((size_t)(b * NF + fs * FSL)) * NT + t0;

#pragma unroll 5
    for (int f = 0; f < FSL; f++) {
        float2 xv = *(const float2*)(base + (size_t)f * NT);
        float th0 = tanh_fast(0.5f * xv.x);
        float th1 = tanh_fast(0.5f * xv.y);
        unsigned long long s01 = pack2(th0, th1);

        const ulonglong2* wv = (const ulonglong2*)&Wp2[f * NO];
        ulonglong2 wa = wv[0];  // o0, o1
        ulonglong2 wb = wv[1];  // o2, o3
        ulonglong2 wc = wv[2];  // o4, o5
        ulonglong2 wd = wv[3];  // o6, o7
        ulonglong2 we = wv[4];  // o8, o9

        fma2(acc[0], s01, wa.x);
        fma2(acc[1], s01, wa.y);
        fma2(acc[2], s01, wb.x);
        fma2(acc[3], s01, wb.y);
        fma2(acc[4], s01, wc.x);
        fma2(acc[5], s01, wc.y);
        fma2(acc[6], s01, wd.x);
        fma2(acc[7], s01, wd.y);
        fma2(acc[8], s01, we.x);
        fma2(acc[9], s01, we.y);
    }

#pragma unroll
    for (int o = 0; o < NO; o++) {
        float lo, hi;
        unpack2(acc[o], lo, hi);
        float c = Cs[o];
        float* p = g_u + ((size_t)((fs * NB + b) * NO + o)) * NT + t0;
        *(float2*)p = make_float2(lo + c, hi + c);
    }
}

// Kernel 2: one block per (b,o) sequence. Coop-load partials into shared,
// single-thread (pipelined) IIR+LIF scan from shared, coop-store spikes.
__global__ __launch_bounds__(256) void scan_kernel(const float* __restrict__ a1p,
                                                   const float* __restrict__ a2p,
                                                   const float* __restrict__ bias,
                                                   float* __restrict__ out) {
    __shared__ __align__(16) float4 ps[NT / 4];
    __shared__ __align__(16) float4 sp[NT / 4];

    const int blk = blockIdx.x;           // 0..NB*NO-1  (= b*NO + o)
    const int tid = threadIdx.x;
    const int o = blk % NO;

    const size_t stride = (size_t)NB * NO * NT;
    const float* u0 = g_u + (size_t)blk * NT;
    const float* u1 = u0 + stride;
    const float* u2 = u1 + stride;
    const float* u3 = u2 + stride;

    // cooperative load + sum of the 4 partials into shared (one float4 per thread)
    {
        int t = tid * 4;
        float4 p0 = *(const float4*)(u0 + t);
        float4 p1 = *(const float4*)(u1 + t);
        float4 p2 = *(const float4*)(u2 + t);
        float4 p3 = *(const float4*)(u3 + t);
        float4 s;
        s.x = (p0.x + p1.x) + (p2.x + p3.x);
        s.y = (p0.y + p1.y) + (p2.y + p3.y);
        s.z = (p0.z + p1.z) + (p2.z + p3.z);
        s.w = (p0.w + p1.w) + (p2.w + p3.w);
        ps[tid] = s;
    }
    __syncthreads();

    if (tid == 0) {
        const float a1 = a1p[0];
        const float a2 = a2p[0];
        const float dm = 0.7788007830714049f;  // exp(-1/4) as f32
        const float bo = bias[o];

        float y1 = 0.0f, y2 = 0.0f;   // IIR state
        float v = 0.0f;               // LIF membrane

        float4 nxt = ps[0];
#pragma unroll 8
        for (int i = 0; i < NT / 4; i++) {
            float4 u4 = nxt;
            int ip = (i + 1 < NT / 4) ? i + 1 : i;
            nxt = ps[ip];                       // prefetch next float4
            float4 s4;
            {
                float y = fmaf(a1, y1, fmaf(a2, y2, u4.x));
                y2 = y1; y1 = y;
                float it = y + bo;
                float vn = fmaf(dm, v, it);
                v = (v > 1.0f) ? it : vn;      // reset-on-spike (prev v's spike)
                s4.x = (v > 1.0f) ? 1.0f : 0.0f;
            }
            {
                float y = fmaf(a1, y1, fmaf(a2, y2, u4.y));
                y2 = y1; y1 = y;
                float it = y + bo;
                float vn = fmaf(dm, v, it);
                v = (v > 1.0f) ? it : vn;
                s4.y = (v > 1.0f) ? 1.0f : 0.0f;
            }
            {
                float y = fmaf(a1, y1, fmaf(a2, y2, u4.z));
                y2 = y1; y1 = y;
                float it = y + bo;
                float vn = fmaf(dm, v, it);
                v = (v > 1.0f) ? it : vn;
                s4.z = (v > 1.0f) ? 1.0f : 0.0f;
            }
            {
                float y = fmaf(a1, y1, fmaf(a2, y2, u4.w));
                y2 = y1; y1 = y;
                float it = y + bo;
                float vn = fmaf(dm, v, it);
                v = (v > 1.0f) ? it : vn;
                s4.w = (v > 1.0f) ? 1.0f : 0.0f;
            }
            sp[i] = s4;
        }
    }
    __syncthreads();

    float* op = out + (size_t)blk * NT;
    *(float4*)(op + tid * 4) = sp[tid];
}

extern "C" void kernel_launch(void* const* d_in, const int* in_sizes, int n_in,
                              void* d_out, int out_size) {
    const float* in = (const float*)d_in[0];   // [64, 500, 1024]
    const float* a1 = (const float*)d_in[1];   // [500]
    const float* a2 = (const float*)d_in[2];   // [500]
    const float* W  = (const float*)d_in[3];   // [10, 500]
    const float* b  = (const float*)d_in[4];   // [10]
    float* out = (float*)d_out;                // [64, 10, 1024]

    dim3 grid1(NT / 128, NB, NFS);
    proj_kernel<<<grid1, 64>>>(in, W);
    scan_kernel<<<NB * NO, 256>>>(a1, a2, b, out);
}

// round 10
// speedup vs baseline: 3.9764x; 1.0503x over previous
#include <cuda_runtime.h>
#include <math.h>

#define NB 64
#define NF 500
#define NT 1024
#define NO 10
#define NFS 4            // F-splits
#define FSL (NF / NFS)   // 125 features per split

// Partial sums: g_u[fs][b][o][t]
__device__ float g_u[NFS * NB * NO * NT];

__device__ __forceinline__ float tanh_fast(float x) {
    float th;
    asm("tanh.approx.f32 %0, %1;" : "=f"(th) : "f"(x));
    return th;
}

#if defined(__CUDA_ARCH__) && (__CUDA_ARCH__ >= 1000)
#define USE_F32X2 1
#else
#define USE_F32X2 0
#endif

__device__ __forceinline__ unsigned long long pack2(float lo, float hi) {
    unsigned long long v;
    asm("mov.b64 %0, {%1, %2};" : "=l"(v) : "f"(lo), "f"(hi));
    return v;
}

__device__ __forceinline__ void unpack2(unsigned long long v, float& lo, float& hi) {
    asm("mov.b64 {%0, %1}, %2;" : "=f"(lo), "=f"(hi) : "l"(v));
}

__device__ __forceinline__ void fma2(unsigned long long& d, unsigned long long a,
                                     unsigned long long b) {
#if USE_F32X2
    asm("fma.rn.f32x2 %0, %1, %2, %0;" : "+l"(d) : "l"(a), "l"(b));
#else
    float dl, dh, al, ah, bl, bh;
    unpack2(d, dl, dh); unpack2(a, al, ah); unpack2(b, bl, bh);
    dl = fmaf(al, bl, dl); dh = fmaf(ah, bh, dh);
    d = pack2(dl, dh);
#endif
}

// Kernel 1: partial projection over one F-slice.
// Grid: (NT/128, NB, NFS); 64 threads/block; each thread owns 2 consecutive t.
// psc_o = sum_f (0.5*w_of)*tanh(0.5*x_f) + C_o,  C_o = sum_f 0.5*w_of
// Explicit depth-4 prefetch keeps 4 LDGs in flight regardless of the tanh chain.
__global__ __launch_bounds__(64) void proj_kernel(const float* __restrict__ in,
                                                  const float* __restrict__ W) {
    __shared__ __align__(16) float2 Wp2[FSL * NO];
    __shared__ float Cs[NO];
    const int tid = threadIdx.x;
    const int fs  = blockIdx.z;

    for (int i = tid; i < FSL * NO; i += 64) {
        int f = i / NO, o = i - f * NO;
        float w = 0.5f * W[o * NF + fs * FSL + f];
        Wp2[f * NO + o] = make_float2(w, w);
    }
    __syncthreads();
    if (tid < NO) {
        float c = 0.0f;
        for (int f = 0; f < FSL; f++) c += Wp2[f * NO + tid].x;
        Cs[tid] = c;
    }
    __syncthreads();

    const int b  = blockIdx.y;
    const int t0 = blockIdx.x * 128 + tid * 2;

    unsigned long long acc[NO];
#pragma unroll
    for (int o = 0; o < NO; o++) acc[o] = 0ULL;

    const float* base = in + ((size_t)(b * NF + fs * FSL)) * NT + t0;

    // prime the prefetch pipeline: 4 rows in flight
    float2 buf[4];
#pragma unroll
    for (int k = 0; k < 4; k++)
        buf[k] = *(const float2*)(base + (size_t)k * NT);

#pragma unroll 4
    for (int f = 0; f < FSL; f++) {
        float2 xv = buf[f & 3];
        int fp = (f + 4 < FSL) ? f + 4 : FSL - 1;     // clamp; value unused at tail
        buf[f & 3] = *(const float2*)(base + (size_t)fp * NT);

        float th0 = tanh_fast(0.5f * xv.x);
        float th1 = tanh_fast(0.5f * xv.y);
        unsigned long long s01 = pack2(th0, th1);

        const ulonglong2* wv = (const ulonglong2*)&Wp2[f * NO];
        ulonglong2 wa = wv[0];  // o0, o1
        ulonglong2 wb = wv[1];  // o2, o3
        ulonglong2 wc = wv[2];  // o4, o5
        ulonglong2 wd = wv[3];  // o6, o7
        ulonglong2 we = wv[4];  // o8, o9

        fma2(acc[0], s01, wa.x);
        fma2(acc[1], s01, wa.y);
        fma2(acc[2], s01, wb.x);
        fma2(acc[3], s01, wb.y);
        fma2(acc[4], s01, wc.x);
        fma2(acc[5], s01, wc.y);
        fma2(acc[6], s01, wd.x);
        fma2(acc[7], s01, wd.y);
        fma2(acc[8], s01, we.x);
        fma2(acc[9], s01, we.y);
    }

#pragma unroll
    for (int o = 0; o < NO; o++) {
        float lo, hi;
        unpack2(acc[o], lo, hi);
        float c = Cs[o];
        float* p = g_u + ((size_t)((fs * NB + b) * NO + o)) * NT + t0;
        *(float2*)p = make_float2(lo + c, hi + c);
    }
}

// one IIR + LIF step; spike selected from precomputed candidates so the
// trailing compare is off the v-critical chain.
#define LIF_STEP(UU, SS)                                        \
    {                                                           \
        float y = fmaf(a1, y1, fmaf(a2, y2, (UU)));             \
        y2 = y1; y1 = y;                                        \
        float it = y + bo;                                      \
        float vn = fmaf(dm, v, it);                             \
        float sit = (it > 1.0f) ? 1.0f : 0.0f;                  \
        float svn = (vn > 1.0f) ? 1.0f : 0.0f;                  \
        bool p = (v > 1.0f);                                    \
        v = p ? it : vn;                                        \
        (SS) = p ? sit : svn;                                   \
    }

// Kernel 2: one block per (b,o) sequence. Coop-load partials into shared,
// single-thread (tight, prefetched) IIR+LIF scan from shared, coop-store spikes.
__global__ __launch_bounds__(256) void scan_kernel(const float* __restrict__ a1p,
                                                   const float* __restrict__ a2p,
                                                   const float* __restrict__ bias,
                                                   float* __restrict__ out) {
    __shared__ __align__(16) float4 ps[NT / 4];
    __shared__ __align__(16) float4 sp[NT / 4];

    const int blk = blockIdx.x;           // 0..NB*NO-1  (= b*NO + o)
    const int tid = threadIdx.x;
    const int o = blk % NO;

    const size_t stride = (size_t)NB * NO * NT;
    const float* u0 = g_u + (size_t)blk * NT;
    const float* u1 = u0 + stride;
    const float* u2 = u1 + stride;
    const float* u3 = u2 + stride;

    // cooperative load + sum of the 4 partials into shared (one float4 per thread)
    {
        int t = tid * 4;
        float4 p0 = *(const float4*)(u0 + t);
        float4 p1 = *(const float4*)(u1 + t);
        float4 p2 = *(const float4*)(u2 + t);
        float4 p3 = *(const float4*)(u3 + t);
        float4 s;
        s.x = (p0.x + p1.x) + (p2.x + p3.x);
        s.y = (p0.y + p1.y) + (p2.y + p3.y);
        s.z = (p0.z + p1.z) + (p2.z + p3.z);
        s.w = (p0.w + p1.w) + (p2.w + p3.w);
        ps[tid] = s;
    }
    __syncthreads();

    if (tid == 0) {
        const float a1 = a1p[0];
        const float a2 = a2p[0];
        const float dm = 0.7788007830714049f;  // exp(-1/4) as f32
        const float bo = bias[o];

        float y1 = 0.0f, y2 = 0.0f;   // IIR state
        float v = 0.0f;               // LIF membrane

        float4 cur = ps[0];
#pragma unroll 4
        for (int i = 0; i < NT / 4 - 1; i++) {
            float4 nxt = ps[i + 1];            // prefetch next float4
            float4 s4;
            LIF_STEP(cur.x, s4.x)
            LIF_STEP(cur.y, s4.y)
            LIF_STEP(cur.z, s4.z)
            LIF_STEP(cur.w, s4.w)
            sp[i] = s4;
            cur = nxt;
        }
        {
            float4 s4;
            LIF_STEP(cur.x, s4.x)
            LIF_STEP(cur.y, s4.y)
            LIF_STEP(cur.z, s4.z)
            LIF_STEP(cur.w, s4.w)
            sp[NT / 4 - 1] = s4;
        }
    }
    __syncthreads();

    float* op = out + (size_t)blk * NT;
    *(float4*)(op + tid * 4) = sp[tid];
}

extern "C" void kernel_launch(void* const* d_in, const int* in_sizes, int n_in,
                              void* d_out, int out_size) {
    const float* in = (const float*)d_in[0];   // [64, 500, 1024]
    const float* a1 = (const float*)d_in[1];   // [500]
    const float* a2 = (const float*)d_in[2];   // [500]
    const float* W  = (const float*)d_in[3];   // [10, 500]
    const float* b  = (const float*)d_in[4];   // [10]
    float* out = (float*)d_out;                // [64, 10, 1024]

    dim3 grid1(NT / 128, NB, NFS);
    proj_kernel<<<grid1, 64>>>(in, W);
    scan_kernel<<<NB * NO, 256>>>(a1, a2, b, out);
}